// round 6
// baseline (speedup 1.0000x reference)
#include <cuda_runtime.h>
#include <cstdint>
#include <mma.h>

using namespace nvcuda;

#define SEL   2
#define Bb    2
#define Cc    256
#define Nn    2304
#define Gg    8
#define CGd   16
#define INTER 128
#define EPSf  1e-5f
#define LOG2E 1.4426950408889634f

// ---------------- packed f32x2 helpers (proj/wconv) ----------------
typedef unsigned long long f2;
__device__ __forceinline__ void unpack2(f2 v, float& lo, float& hi) {
    asm("mov.b64 {%0,%1},%2;" : "=f"(lo), "=f"(hi) : "l"(v));
}
__device__ __forceinline__ f2 fma2(f2 a, f2 b, f2 c) {
    f2 d; asm("fma.rn.f32x2 %0,%1,%2,%3;" : "=l"(d) : "l"(a), "l"(b), "l"(c)); return d;
}
struct __align__(16) F4 { f2 a, b; };

// ---------------- scratch ----------------
__device__ float g_theta[SEL*Bb*Gg*CGd*Nn];   // pre-scaled by log2e, [bg][d][n]
__device__ float g_phiT [SEL*Bb*Gg*CGd*Nn];
__device__ float g_gx   [SEL*Bb*Gg*CGd*Nn];
__device__ float g_outc [SEL*Bb*INTER*Nn];
__device__ float g_wy   [SEL*Bb*Cc*Nn];
__device__ float g_mean [SEL*Cc];
__device__ float g_rstd [SEL*Cc];

__device__ __forceinline__ float tf32_hi(float x) {
    uint32_t u; asm("cvt.rna.tf32.f32 %0, %1;" : "=r"(u) : "f"(x));
    return __uint_as_float(u);
}
__device__ __forceinline__ float exp2f_fast(float t) {
    float z = t + 12582912.0f;
    int   r = __float_as_int(z) - 0x4b400000;
    float f = t - (z - 12582912.0f);
    float p = 1.3333558e-3f;
    p = fmaf(p, f, 9.6181291e-3f);
    p = fmaf(p, f, 5.5504109e-2f);
    p = fmaf(p, f, 2.4022651e-1f);
    p = fmaf(p, f, 6.9314718e-1f);
    p = fmaf(p, f, 1.0f);
    return __int_as_float(__float_as_int(p) + (r << 23));
}

// ---------------- Kernel 1: grouped projections ----------------
struct ProjArgs {
    const float* x[2];
    const float* tw[2]; const float* tb[2];
    const float* pw[2]; const float* pb[2];
    const float* gw[2]; const float* gb[2];
};

__global__ __launch_bounds__(128) void proj_kernel(ProjArgs A)
{
    int tid = threadIdx.x;
    int n0  = blockIdx.x * 256;
    int g   = blockIdx.y;
    int sb  = blockIdx.z;
    int sel = sb >> 1, b = sb & 1;

    const float* tw = A.tw[sel]; const float* pw = A.pw[sel]; const float* gw = A.gw[sel];

    __shared__ __align__(16) float2 Xs[32 * 128];
    __shared__ __align__(16) float2 Ws[48 * 32];

    f2 acc[48];
    #pragma unroll
    for (int j = 0; j < 48; ++j) acc[j] = 0ULL;

    const float* xb = A.x[sel] + b * (Cc * Nn) + n0 + 2 * tid;

    for (int c0 = 0; c0 < Cc; c0 += 32) {
        #pragma unroll 8
        for (int c = 0; c < 32; ++c)
            Xs[c * 128 + tid] = *(const float2*)(xb + (c0 + c) * Nn);
        #pragma unroll
        for (int r = 0; r < 12; ++r) {
            int idx = tid + r * 128;
            int j = idx >> 5, k = idx & 31;
            const float* wsrc = (j < 16) ? (tw + (g*CGd + j)      * Cc)
                              : (j < 32) ? (pw + (g*CGd + (j-16)) * Cc)
                                         : (gw + (g*CGd + (j-32)) * Cc);
            float w = wsrc[c0 + k];
            Ws[j * 32 + k] = make_float2(w, w);
        }
        __syncthreads();
        #pragma unroll 2
        for (int k = 0; k < 32; k += 2) {
            f2 xv0 = *(const f2*)&Xs[k * 128 + tid];
            f2 xv1 = *(const f2*)&Xs[(k + 1) * 128 + tid];
            #pragma unroll
            for (int j = 0; j < 48; ++j) {
                F4 w = *(const F4*)&Ws[j * 32 + k];
                acc[j] = fma2(w.a, xv0, acc[j]);
                acc[j] = fma2(w.b, xv1, acc[j]);
            }
        }
        __syncthreads();
    }

    int bg = sb * Gg + g;
    int nq = n0 + 2 * tid;
    const float* tb = A.tb[sel]; const float* pb = A.pb[sel]; const float* gb = A.gb[sel];
    #pragma unroll
    for (int m = 0; m < 16; ++m) {
        float lo, hi;
        unpack2(acc[m], lo, hi);
        float bt = tb[g*CGd + m];
        *(float2*)(g_theta + (bg*CGd + m) * Nn + nq) =
            make_float2((lo + bt) * LOG2E, (hi + bt) * LOG2E);
        unpack2(acc[16 + m], lo, hi);
        float bp = pb[g*CGd + m];
        *(float2*)(g_phiT + (bg*CGd + m) * Nn + nq) = make_float2(lo + bp, hi + bp);
        unpack2(acc[32 + m], lo, hi);
        float bgg = gb[g*CGd + m];
        *(float2*)(g_gx + (bg*CGd + m) * Nn + nq) = make_float2(lo + bgg, hi + bgg);
    }
}

// ---------------- Kernel 2: wmma tf32 flash attention ----------------
// CTA = (bg, 128-query tile); 128 thr (4 warps); grid (18, G, SEL*B).
// S = [θh|θh|θl]·[φh|φl|φh]ᵀ (K=48 3-term split); P = exp2(S) in smem (fp32,
// HW-truncated to tf32 in PV — cancels in softmax ratio);
// O += P·[Vh | 1 | 0 | Vl | 0pad] (N=48; col 16 = denominator).
#define QK_LD  52           // 48 + 4 pad
#define PV_LD  132          // 128 + 4 pad
#define SM_Q   0                            // 128 x QK_LD
#define SM_K   (128*QK_LD)                  // 128 x QK_LD
#define SM_V   (2*128*QK_LD)                // 48 x PV_LD
#define SM_P   (2*128*QK_LD + 48*PV_LD)     // 128 x PV_LD
#define ATTN_SMEM ((2*128*QK_LD + 48*PV_LD + 128*PV_LD) * 4)

__global__ __launch_bounds__(128, 1) void attn_wmma_kernel()
{
    extern __shared__ float sm[];
    float* Qs = sm + SM_Q;
    float* Ks = sm + SM_K;
    float* Vs = sm + SM_V;
    float* Ps = sm + SM_P;

    int tid = threadIdx.x, wid = tid >> 5;
    int g = blockIdx.y, sbz = blockIdx.z;
    int bg = sbz * Gg + g;
    int n0 = blockIdx.x * 128;
    const float* th = g_theta + bg * CGd * Nn;
    const float* ks = g_phiT  + bg * CGd * Nn;
    const float* vs = g_gx    + bg * CGd * Nn;

    // Q: row tid = query; cols [θh | θh | θl]
    {
        float* q = Qs + tid * QK_LD;
        #pragma unroll
        for (int d = 0; d < 16; ++d) {
            float v = th[d * Nn + n0 + tid];
            float hi = tf32_hi(v), lo = v - hi;
            q[d] = hi; q[16 + d] = hi; q[32 + d] = lo;
        }
    }
    // V constant rows: 16 = ones; 17..23, 40..47 = zero
    {
        #pragma unroll
        for (int n = 16; n < 24; ++n)
            Vs[n * PV_LD + tid] = (n == 16) ? 1.0f : 0.0f;
        #pragma unroll
        for (int n = 40; n < 48; ++n)
            Vs[n * PV_LD + tid] = 0.0f;
    }

    wmma::fragment<wmma::accumulator, 16, 16, 8, float> O[2][3];
    #pragma unroll
    for (int mi = 0; mi < 2; ++mi)
        #pragma unroll
        for (int nt = 0; nt < 3; ++nt)
            wmma::fill_fragment(O[mi][nt], 0.0f);

    __syncthreads();

    for (int t = 0; t < 18; ++t) {
        // fill K tile (row tid = key): [φh | φl | φh];  V tile: rows d = Vh, 24+d = Vl
        {
            int key = t * 128 + tid;
            float* kr = Ks + tid * QK_LD;
            #pragma unroll
            for (int d = 0; d < 16; ++d) {
                float v = ks[d * Nn + key];
                float hi = tf32_hi(v), lo = v - hi;
                kr[d] = hi; kr[16 + d] = lo; kr[32 + d] = hi;
                float vv = vs[d * Nn + key];
                float vh = tf32_hi(vv);
                Vs[d * PV_LD + tid] = vh;
                Vs[(24 + d) * PV_LD + tid] = vv - vh;
            }
        }
        __syncthreads();

        // S phase: warp rows [wid*32, wid*32+32)
        #pragma unroll
        for (int mi = 0; mi < 2; ++mi) {
            wmma::fragment<wmma::accumulator, 16, 16, 8, float> C[8];
            #pragma unroll
            for (int nt = 0; nt < 8; ++nt) wmma::fill_fragment(C[nt], 0.0f);
            const float* arow = Qs + (wid * 32 + mi * 16) * QK_LD;
            #pragma unroll
            for (int kk = 0; kk < 6; ++kk) {
                wmma::fragment<wmma::matrix_a, 16, 16, 8, wmma::precision::tf32, wmma::row_major> A;
                wmma::load_matrix_sync(A, arow + kk * 8, QK_LD);
                #pragma unroll
                for (int nt = 0; nt < 8; ++nt) {
                    wmma::fragment<wmma::matrix_b, 16, 16, 8, wmma::precision::tf32, wmma::col_major> B;
                    wmma::load_matrix_sync(B, Ks + (nt * 16) * QK_LD + kk * 8, QK_LD);
                    wmma::mma_sync(C[nt], A, B, C[nt]);
                }
            }
            #pragma unroll
            for (int nt = 0; nt < 8; ++nt)
                wmma::store_matrix_sync(Ps + (wid * 32 + mi * 16) * PV_LD + nt * 16,
                                        C[nt], PV_LD, wmma::mem_row_major);
        }
        __syncthreads();

        // exp phase: column tid across all 128 rows (conflict-free)
        #pragma unroll 4
        for (int r = 0; r < 128; ++r)
            Ps[r * PV_LD + tid] = exp2f_fast(Ps[r * PV_LD + tid]);
        __syncthreads();

        // PV phase: O += P · V
        #pragma unroll
        for (int kk = 0; kk < 16; ++kk) {
            wmma::fragment<wmma::matrix_a, 16, 16, 8, wmma::precision::tf32, wmma::row_major> A0, A1;
            wmma::load_matrix_sync(A0, Ps + (wid * 32) * PV_LD + kk * 8, PV_LD);
            wmma::load_matrix_sync(A1, Ps + (wid * 32 + 16) * PV_LD + kk * 8, PV_LD);
            #pragma unroll
            for (int nt = 0; nt < 3; ++nt) {
                wmma::fragment<wmma::matrix_b, 16, 16, 8, wmma::precision::tf32, wmma::col_major> B;
                wmma::load_matrix_sync(B, Vs + (nt * 16) * PV_LD + kk * 8, PV_LD);
                wmma::mma_sync(O[0][nt], A0, B, O[0][nt]);
                wmma::mma_sync(O[1][nt], A1, B, O[1][nt]);
            }
        }
        __syncthreads();
    }

    // epilogue: dump O to Ps, then per-row normalize
    #pragma unroll
    for (int mi = 0; mi < 2; ++mi)
        #pragma unroll
        for (int nt = 0; nt < 3; ++nt)
            wmma::store_matrix_sync(Ps + (wid * 32 + mi * 16) * PV_LD + nt * 16,
                                    O[mi][nt], PV_LD, wmma::mem_row_major);
    __syncthreads();

    {
        const float* row = Ps + tid * PV_LD;
        float inv = 1.0f / row[16];
        int chan = sbz * INTER + g * CGd;
        #pragma unroll
        for (int d = 0; d < 16; ++d)
            g_outc[(chan + d) * Nn + n0 + tid] = (row[d] + row[24 + d]) * inv;
    }
}

// ---------------- Kernel 3: W conv (GEMM) ----------------
struct WArgs { const float* Ww[2]; const float* Wb[2]; };

__global__ __launch_bounds__(128) void wconv_kernel(WArgs A)
{
    int tid = threadIdx.x;
    int n0  = blockIdx.x * 256;
    int o0  = blockIdx.y * 32;
    int sb  = blockIdx.z;
    int sel = sb >> 1;

    __shared__ __align__(16) float2 Xs[32 * 128];
    __shared__ __align__(16) float2 Ws[32 * 32];

    f2 acc[32];
    #pragma unroll
    for (int j = 0; j < 32; ++j) acc[j] = 0ULL;

    const float* src = g_outc + sb * (INTER * Nn) + n0 + 2 * tid;
    const float* Ww = A.Ww[sel];

    for (int i0 = 0; i0 < INTER; i0 += 32) {
        #pragma unroll 8
        for (int k = 0; k < 32; ++k)
            Xs[k * 128 + tid] = *(const float2*)(src + (i0 + k) * Nn);
        #pragma unroll
        for (int r = 0; r < 8; ++r) {
            int idx = tid + r * 128;
            int j = idx >> 5, k = idx & 31;
            float w = Ww[(o0 + j) * INTER + i0 + k];
            Ws[j * 32 + k] = make_float2(w, w);
        }
        __syncthreads();
        #pragma unroll 2
        for (int k = 0; k < 32; k += 2) {
            f2 xv0 = *(const f2*)&Xs[k * 128 + tid];
            f2 xv1 = *(const f2*)&Xs[(k + 1) * 128 + tid];
            #pragma unroll
            for (int j = 0; j < 32; ++j) {
                F4 w = *(const F4*)&Ws[j * 32 + k];
                acc[j] = fma2(w.a, xv0, acc[j]);
                acc[j] = fma2(w.b, xv1, acc[j]);
            }
        }
        __syncthreads();
    }

    float* dst = g_wy + sb * (Cc * Nn) + n0 + 2 * tid;
    const float* Wb = A.Wb[sel];
    #pragma unroll
    for (int j = 0; j < 32; ++j) {
        float lo, hi;
        unpack2(acc[j], lo, hi);
        float bb = Wb[o0 + j];
        *(float2*)(dst + (o0 + j) * Nn) = make_float2(lo + bb, hi + bb);
    }
}

// ---------------- Kernel 4: BN stats ----------------
__global__ __launch_bounds__(256) void stats_kernel()
{
    int sel = blockIdx.x / Cc;
    int o   = blockIdx.x % Cc;
    int tid = threadIdx.x;
    const float4* r0 = (const float4*)(g_wy + ((sel*Bb + 0) * Cc + o) * Nn);
    const float4* r1 = (const float4*)(g_wy + ((sel*Bb + 1) * Cc + o) * Nn);

    float s = 0.f, s2 = 0.f;
    for (int i = tid; i < Nn/4; i += 256) {
        float4 a = r0[i], c = r1[i];
        s += a.x + a.y + a.z + a.w;
        s += c.x + c.y + c.z + c.w;
        s2 = fmaf(a.x, a.x, s2); s2 = fmaf(a.y, a.y, s2);
        s2 = fmaf(a.z, a.z, s2); s2 = fmaf(a.w, a.w, s2);
        s2 = fmaf(c.x, c.x, s2); s2 = fmaf(c.y, c.y, s2);
        s2 = fmaf(c.z, c.z, s2); s2 = fmaf(c.w, c.w, s2);
    }
    __shared__ float sh[256], sh2[256];
    sh[tid] = s; sh2[tid] = s2;
    __syncthreads();
    for (int st = 128; st > 0; st >>= 1) {
        if (tid < st) { sh[tid] += sh[tid + st]; sh2[tid] += sh2[tid + st]; }
        __syncthreads();
    }
    if (tid == 0) {
        float mean = sh[0] * (1.0f / (Bb * Nn));
        float var  = sh2[0] * (1.0f / (Bb * Nn)) - mean * mean;
        g_mean[blockIdx.x] = mean;
        g_rstd[blockIdx.x] = rsqrtf(var + EPSf);
    }
}

// ---------------- Kernel 5: BN apply + residual + ReLU ----------------
struct ApplyArgs {
    const float* x[2];
    const float* gam[2]; const float* bet[2];
};

__global__ __launch_bounds__(256) void apply_kernel(ApplyArgs A, float* __restrict__ out)
{
    int i4 = blockIdx.x * 256 + threadIdx.x;
    int idx = i4 * 4;
    int per = Bb * Cc * Nn;
    int sel = idx / per;
    int loc = idx - sel * per;
    int o   = (loc / Nn) % Cc;
    float m  = g_mean[sel*Cc + o];
    float rs = g_rstd[sel*Cc + o];
    float ga = A.gam[sel][o], be = A.bet[sel][o];
    float4 wv = *(const float4*)(g_wy + idx);
    float4 xv = *(const float4*)(A.x[sel] + loc);
    float4 r;
    r.x = fmaxf(fmaf((wv.x - m) * rs, ga, be) + xv.x, 0.f);
    r.y = fmaxf(fmaf((wv.y - m) * rs, ga, be) + xv.y, 0.f);
    r.z = fmaxf(fmaf((wv.z - m) * rs, ga, be) + xv.z, 0.f);
    r.w = fmaxf(fmaf((wv.w - m) * rs, ga, be) + xv.w, 0.f);
    *(float4*)(out + idx) = r;
}

// ---------------- launch ----------------
extern "C" void kernel_launch(void* const* d_in, const int* in_sizes, int n_in,
                              void* d_out, int out_size)
{
    ProjArgs P; WArgs W; ApplyArgs AP;
    for (int s = 0; s < 2; ++s) {
        P.x[s]  = (const float*)d_in[s];
        P.gw[s] = (const float*)d_in[2 + s*10 + 0];
        P.gb[s] = (const float*)d_in[2 + s*10 + 1];
        P.tw[s] = (const float*)d_in[2 + s*10 + 2];
        P.tb[s] = (const float*)d_in[2 + s*10 + 3];
        P.pw[s] = (const float*)d_in[2 + s*10 + 4];
        P.pb[s] = (const float*)d_in[2 + s*10 + 5];
        W.Ww[s] = (const float*)d_in[2 + s*10 + 6];
        W.Wb[s] = (const float*)d_in[2 + s*10 + 7];
        AP.x[s]   = (const float*)d_in[s];
        AP.gam[s] = (const float*)d_in[2 + s*10 + 8];
        AP.bet[s] = (const float*)d_in[2 + s*10 + 9];
    }

    static int smem_set = 0;
    if (!smem_set) {
        cudaFuncSetAttribute(attn_wmma_kernel,
                             cudaFuncAttributeMaxDynamicSharedMemorySize, ATTN_SMEM);
        smem_set = 1;
    }

    proj_kernel     <<<dim3(9, Gg, SEL*Bb), 128>>>(P);
    attn_wmma_kernel<<<dim3(18, Gg, SEL*Bb), 128, ATTN_SMEM>>>();
    wconv_kernel    <<<dim3(9, Cc/32, SEL*Bb), 128>>>(W);
    stats_kernel    <<<SEL*Cc, 256>>>();
    apply_kernel    <<<(SEL*Bb*Cc*Nn)/1024, 256>>>(AP, (float*)d_out);
}

// round 8
// speedup vs baseline: 3.4443x; 3.4443x over previous
#include <cuda_runtime.h>
#include <cstdint>

typedef unsigned int u32;
typedef unsigned short u16;

#define SEL   2
#define Bb    2
#define Cc    256
#define Nn    2304
#define Gg    8
#define CGd   16
#define INTER 128
#define EPSf  1e-5f
#define LOG2E 1.4426950408889634f

// ---------------- packed f32x2 helpers (proj/wconv) ----------------
typedef unsigned long long f2;
__device__ __forceinline__ void unpack2(f2 v, float& lo, float& hi) {
    asm("mov.b64 {%0,%1},%2;" : "=f"(lo), "=f"(hi) : "l"(v));
}
__device__ __forceinline__ f2 fma2(f2 a, f2 b, f2 c) {
    f2 d; asm("fma.rn.f32x2 %0,%1,%2,%3;" : "=l"(d) : "l"(a), "l"(b), "l"(c)); return d;
}
struct __align__(16) F4 { f2 a, b; };

// ---------------- scratch ----------------
__device__ u16  g_thQ[SEL*Bb*Gg*Nn*32];     // [bg][n][16 hi | 16 lo], theta*log2e, bf16
__device__ u16  g_phK[SEL*Bb*Gg*Nn*32];     // [bg][n][16 hi | 16 lo], phi, bf16
__device__ u16  g_vH [SEL*Bb*Gg*CGd*Nn];    // [bg][d][n] bf16 hi
__device__ u16  g_vL [SEL*Bb*Gg*CGd*Nn];    // [bg][d][n] bf16 lo
__device__ float g_outc[SEL*Bb*INTER*Nn];
__device__ float g_wy  [SEL*Bb*Cc*Nn];
__device__ float g_mean[SEL*Cc];
__device__ float g_rstd[SEL*Cc];

// ---------------- helpers ----------------
__device__ __forceinline__ u32 smem_u32(const void* p) {
    u32 a;
    asm("{ .reg .u64 t; cvta.to.shared.u64 t, %1; cvt.u32.u64 %0, t; }" : "=r"(a) : "l"(p));
    return a;
}
__device__ __forceinline__ u32 cvt2bf(float hi, float lo) {
    u32 d; asm("cvt.rn.bf16x2.f32 %0, %1, %2;" : "=r"(d) : "f"(hi), "f"(lo)); return d;
}
__device__ __forceinline__ float bflo(u32 w) { return __uint_as_float(w << 16); }
__device__ __forceinline__ float bfhi(u32 w) { return __uint_as_float(w & 0xFFFF0000u); }

__device__ __forceinline__ void ldsm4(u32* r, u32 a) {
    asm volatile("ldmatrix.sync.aligned.m8n8.x4.shared.b16 {%0,%1,%2,%3}, [%4];"
        : "=r"(r[0]), "=r"(r[1]), "=r"(r[2]), "=r"(r[3]) : "r"(a));
}
__device__ __forceinline__ void ldsm2(u32* r, u32 a) {
    asm volatile("ldmatrix.sync.aligned.m8n8.x2.shared.b16 {%0,%1}, [%2];"
        : "=r"(r[0]), "=r"(r[1]) : "r"(a));
}
__device__ __forceinline__ void mma_bf16(float* c, const u32* a, const u32* b) {
    asm volatile("mma.sync.aligned.m16n8k16.row.col.f32.bf16.bf16.f32 "
        "{%0,%1,%2,%3}, {%4,%5,%6,%7}, {%8,%9}, {%0,%1,%2,%3};"
        : "+f"(c[0]), "+f"(c[1]), "+f"(c[2]), "+f"(c[3])
        : "r"(a[0]), "r"(a[1]), "r"(a[2]), "r"(a[3]), "r"(b[0]), "r"(b[1]));
}
__device__ __forceinline__ float exp2f_fast(float t) {
    float z = t + 12582912.0f;
    int   r = __float_as_int(z) - 0x4b400000;
    float f = t - (z - 12582912.0f);
    float p = 1.3333558e-3f;
    p = fmaf(p, f, 9.6181291e-3f);
    p = fmaf(p, f, 5.5504109e-2f);
    p = fmaf(p, f, 2.4022651e-1f);
    p = fmaf(p, f, 6.9314718e-1f);
    p = fmaf(p, f, 1.0f);
    return __int_as_float(__float_as_int(p) + (r << 23));
}

// ---------------- Kernel 1: grouped projections -> bf16 hi/lo tensors ----------------
struct ProjArgs {
    const float* x[2];
    const float* tw[2]; const float* tb[2];
    const float* pw[2]; const float* pb[2];
    const float* gw[2]; const float* gb[2];
};

__global__ __launch_bounds__(128) void proj_kernel(ProjArgs A)
{
    int tid = threadIdx.x;
    int n0  = blockIdx.x * 256;
    int g   = blockIdx.y;
    int sb  = blockIdx.z;
    int sel = sb >> 1, b = sb & 1;

    const float* tw = A.tw[sel]; const float* pw = A.pw[sel]; const float* gw = A.gw[sel];

    __shared__ __align__(16) float2 Xs[32 * 128];
    __shared__ __align__(16) float2 Ws[48 * 32];

    f2 acc[48];
    #pragma unroll
    for (int j = 0; j < 48; ++j) acc[j] = 0ULL;

    const float* xb = A.x[sel] + b * (Cc * Nn) + n0 + 2 * tid;

    for (int c0 = 0; c0 < Cc; c0 += 32) {
        #pragma unroll 8
        for (int c = 0; c < 32; ++c)
            Xs[c * 128 + tid] = *(const float2*)(xb + (c0 + c) * Nn);
        #pragma unroll
        for (int r = 0; r < 12; ++r) {
            int idx = tid + r * 128;
            int j = idx >> 5, k = idx & 31;
            const float* wsrc = (j < 16) ? (tw + (g*CGd + j)      * Cc)
                              : (j < 32) ? (pw + (g*CGd + (j-16)) * Cc)
                                         : (gw + (g*CGd + (j-32)) * Cc);
            float w = wsrc[c0 + k];
            Ws[j * 32 + k] = make_float2(w, w);
        }
        __syncthreads();
        #pragma unroll 2
        for (int k = 0; k < 32; k += 2) {
            f2 xv0 = *(const f2*)&Xs[k * 128 + tid];
            f2 xv1 = *(const f2*)&Xs[(k + 1) * 128 + tid];
            #pragma unroll
            for (int j = 0; j < 48; ++j) {
                F4 w = *(const F4*)&Ws[j * 32 + k];
                acc[j] = fma2(w.a, xv0, acc[j]);
                acc[j] = fma2(w.b, xv1, acc[j]);
            }
        }
        __syncthreads();
    }

    int bg = sb * Gg + g;
    int nq = n0 + 2 * tid;
    const float* tb = A.tb[sel]; const float* pb = A.pb[sel]; const float* gb = A.gb[sel];

    // theta / phi rows: [n][16 hi | 16 lo]
    #pragma unroll
    for (int e = 0; e < 2; ++e) {
        u32 w[16];
        // theta (pre-scaled by log2e)
        #pragma unroll
        for (int j = 0; j < 8; ++j) {
            float l0, h0, l1, h1;
            unpack2(acc[2*j],     l0, h0);
            unpack2(acc[2*j + 1], l1, h1);
            float v0 = ((e ? h0 : l0) + tb[g*CGd + 2*j])     * LOG2E;
            float v1 = ((e ? h1 : l1) + tb[g*CGd + 2*j + 1]) * LOG2E;
            u32 ww = cvt2bf(v1, v0);
            w[j] = ww;
            w[8 + j] = cvt2bf(v1 - bfhi(ww), v0 - bflo(ww));
        }
        {
            uint4* dst = (uint4*)(g_thQ + (size_t)(bg * Nn + nq + e) * 32);
            dst[0] = make_uint4(w[0], w[1], w[2], w[3]);
            dst[1] = make_uint4(w[4], w[5], w[6], w[7]);
            dst[2] = make_uint4(w[8], w[9], w[10], w[11]);
            dst[3] = make_uint4(w[12], w[13], w[14], w[15]);
        }
        // phi
        #pragma unroll
        for (int j = 0; j < 8; ++j) {
            float l0, h0, l1, h1;
            unpack2(acc[16 + 2*j],     l0, h0);
            unpack2(acc[16 + 2*j + 1], l1, h1);
            float v0 = (e ? h0 : l0) + pb[g*CGd + 2*j];
            float v1 = (e ? h1 : l1) + pb[g*CGd + 2*j + 1];
            u32 ww = cvt2bf(v1, v0);
            w[j] = ww;
            w[8 + j] = cvt2bf(v1 - bfhi(ww), v0 - bflo(ww));
        }
        {
            uint4* dst = (uint4*)(g_phK + (size_t)(bg * Nn + nq + e) * 32);
            dst[0] = make_uint4(w[0], w[1], w[2], w[3]);
            dst[1] = make_uint4(w[4], w[5], w[6], w[7]);
            dst[2] = make_uint4(w[8], w[9], w[10], w[11]);
            dst[3] = make_uint4(w[12], w[13], w[14], w[15]);
        }
    }
    // V: [d][n] hi/lo
    #pragma unroll
    for (int d = 0; d < 16; ++d) {
        float l, h;
        unpack2(acc[32 + d], l, h);
        float bv = gb[g*CGd + d];
        float v0 = l + bv, v1 = h + bv;
        u32 ww = cvt2bf(v1, v0);
        *(u32*)(g_vH + (size_t)(bg * CGd + d) * Nn + nq) = ww;
        *(u32*)(g_vL + (size_t)(bg * CGd + d) * Nn + nq) = cvt2bf(v1 - bfhi(ww), v0 - bflo(ww));
    }
}

// ---------------- Kernel 2: bf16 mma.sync flash attention ----------------
// CTA = (bg, 128 queries), 128 threads (4 warps, 32 query rows each).
// S = QhKh + QhKl + QlKh (fp32 accum); P = exp2(S) in regs -> bf16 hi/lo A-frags;
// O += PhVh + PlVh + PhVl; V row 16 = ones (denominator), rows 17-23 = 0.
#define QLD 40              // row stride (u16 elems) for Q/K tiles: 16h+16l+8pad = 80B
#define VLD 136             // V row stride: 128 keys + 8 pad = 272B
#define OQ  0
#define OK  10240
#define OVH 20480
#define OVL 27008
#define SMSZ 31360

__global__ __launch_bounds__(128) void attn_mma_kernel()
{
    __shared__ __align__(16) char SM[SMSZ];
    u16* Qs = (u16*)(SM + OQ);
    u16* Ks = (u16*)(SM + OK);
    u16* VHs = (u16*)(SM + OVH);
    u16* VLs = (u16*)(SM + OVL);

    int tid = threadIdx.x, lane = tid & 31, wid = tid >> 5;
    int g = blockIdx.y, sbz = blockIdx.z;
    int bg = sbz * Gg + g;
    int n0 = blockIdx.x * 128;

    const u16* thq = g_thQ + (size_t)bg * Nn * 32;
    const u16* phk = g_phK + (size_t)bg * Nn * 32;
    const u16* vh  = g_vH + (size_t)bg * CGd * Nn;
    const u16* vl  = g_vL + (size_t)bg * CGd * Nn;

    // Q fill (once): row tid
    {
        const uint4* src = (const uint4*)(thq + (size_t)(n0 + tid) * 32);
        uint4* dst = (uint4*)(Qs + tid * QLD);
        dst[0] = src[0]; dst[1] = src[1]; dst[2] = src[2]; dst[3] = src[3];
    }
    // VH constant rows 16..23 (row 16 = ones)
    #pragma unroll
    for (int i = 0; i < 8; ++i) {
        int r = 16 + i;
        VHs[r * VLD + tid] = (r == 16) ? (u16)0x3F80 : (u16)0;
    }
    __syncthreads();

    u32 SMB = smem_u32(SM);
    u32 QB = SMB + OQ, KB = SMB + OK, VHB = SMB + OVH, VLB = SMB + OVL;

    // Q A-fragments (persistent). Row = [16 hi (bytes 0-31) | 16 lo (bytes 32-63) | pad]
    u32 qh[2][4], ql[2][4];
    {
        int ar  = (lane & 7) + ((lane >> 3) & 1) * 8;
        int acb = (lane >> 4) * 16;
        #pragma unroll
        for (int mi = 0; mi < 2; ++mi) {
            u32 ad = QB + (u32)(wid * 32 + mi * 16 + ar) * 80 + acb;
            ldsm4(qh[mi], ad);
            ldsm4(ql[mi], ad + 32);      // lo half starts at byte 32 (was +64: pad garbage)
        }
    }

    float O[2][3][4];
    #pragma unroll
    for (int mi = 0; mi < 2; ++mi)
        #pragma unroll
        for (int nt = 0; nt < 3; ++nt)
            #pragma unroll
            for (int q = 0; q < 4; ++q) O[mi][nt][q] = 0.f;

    int krow_off = (lane & 7);
    int kcb = ((lane >> 3) & 1) * 16;

    for (int t = 0; t < 18; ++t) {
        int t0 = t * 128;
        // K tile fill: row tid = key
        {
            const uint4* src = (const uint4*)(phk + (size_t)(t0 + tid) * 32);
            uint4* dst = (uint4*)(Ks + tid * QLD);
            dst[0] = src[0]; dst[1] = src[1]; dst[2] = src[2]; dst[3] = src[3];
        }
        // V tiles: thread -> d = tid>>3, key-block = (tid&7)*16
        {
            int d = tid >> 3, blk = (tid & 7) * 16;
            const uint4* sh = (const uint4*)(vh + (size_t)d * Nn + t0 + blk);
            const uint4* sl = (const uint4*)(vl + (size_t)d * Nn + t0 + blk);
            uint4* dh = (uint4*)(VHs + d * VLD + blk);
            uint4* dl = (uint4*)(VLs + d * VLD + blk);
            dh[0] = sh[0]; dh[1] = sh[1];
            dl[0] = sl[0]; dl[1] = sl[1];
        }
        __syncthreads();

        #pragma unroll 2
        for (int c = 0; c < 8; ++c) {
            // K B-fragments (hi/lo) for 2 n8 subtiles
            u32 khb[2][2], klb[2][2];
            #pragma unroll
            for (int s = 0; s < 2; ++s) {
                u32 a = KB + (u32)(c * 16 + 8 * s + krow_off) * 80 + kcb;
                ldsm2(khb[s], a);
                ldsm2(klb[s], a + 32);
            }
            // S = QhKh + QhKl + QlKh
            float C[2][2][4];
            #pragma unroll
            for (int mi = 0; mi < 2; ++mi)
                #pragma unroll
                for (int s = 0; s < 2; ++s) {
                    C[mi][s][0] = 0.f; C[mi][s][1] = 0.f; C[mi][s][2] = 0.f; C[mi][s][3] = 0.f;
                    mma_bf16(C[mi][s], qh[mi], khb[s]);
                    mma_bf16(C[mi][s], qh[mi], klb[s]);
                    mma_bf16(C[mi][s], ql[mi], khb[s]);
                }
            // exp2 + build P hi/lo A-fragments
            u32 pha[2][4], pla[2][4];
            #pragma unroll
            for (int mi = 0; mi < 2; ++mi)
                #pragma unroll
                for (int s = 0; s < 2; ++s) {
                    float p0 = exp2f_fast(C[mi][s][0]);
                    float p1 = exp2f_fast(C[mi][s][1]);
                    float p2 = exp2f_fast(C[mi][s][2]);
                    float p3 = exp2f_fast(C[mi][s][3]);
                    u32 w01 = cvt2bf(p1, p0);
                    u32 w23 = cvt2bf(p3, p2);
                    pha[mi][2*s]     = w01;
                    pha[mi][2*s + 1] = w23;
                    pla[mi][2*s]     = cvt2bf(p1 - bfhi(w01), p0 - bflo(w01));
                    pla[mi][2*s + 1] = cvt2bf(p3 - bfhi(w23), p2 - bflo(w23));
                }
            // V B-fragments
            u32 vhbf[3][2], vlbf[2][2];
            {
                u32 vbase = (u32)(krow_off) * 272 + (u32)kcb + (u32)c * 32;
                #pragma unroll
                for (int nt = 0; nt < 3; ++nt)
                    ldsm2(vhbf[nt], VHB + vbase + (u32)nt * 8 * 272);
                #pragma unroll
                for (int nt = 0; nt < 2; ++nt)
                    ldsm2(vlbf[nt], VLB + vbase + (u32)nt * 8 * 272);
            }
            // O += PhVh + PlVh + PhVl
            #pragma unroll
            for (int mi = 0; mi < 2; ++mi) {
                #pragma unroll
                for (int nt = 0; nt < 3; ++nt) {
                    mma_bf16(O[mi][nt], pha[mi], vhbf[nt]);
                    mma_bf16(O[mi][nt], pla[mi], vhbf[nt]);
                }
                #pragma unroll
                for (int nt = 0; nt < 2; ++nt)
                    mma_bf16(O[mi][nt], pha[mi], vlbf[nt]);
            }
        }
        __syncthreads();
    }

    // Epilogue: dump O frags to smem (f32, stride 26), normalize per row
    float* Es = (float*)(SM + OK);
    {
        int gq = lane >> 2, tg = lane & 3;
        #pragma unroll
        for (int mi = 0; mi < 2; ++mi)
            #pragma unroll
            for (int nt = 0; nt < 3; ++nt) {
                int r = wid * 32 + mi * 16 + gq;
                int col = nt * 8 + 2 * tg;
                Es[r * 26 + col]           = O[mi][nt][0];
                Es[r * 26 + col + 1]       = O[mi][nt][1];
                Es[(r + 8) * 26 + col]     = O[mi][nt][2];
                Es[(r + 8) * 26 + col + 1] = O[mi][nt][3];
            }
    }
    __syncthreads();
    {
        float inv = 1.0f / Es[tid * 26 + 16];
        int chan = sbz * INTER + g * CGd;
        #pragma unroll
        for (int d = 0; d < 16; ++d)
            g_outc[(size_t)(chan + d) * Nn + n0 + tid] = Es[tid * 26 + d] * inv;
    }
}

// ---------------- Kernel 3: W conv (GEMM) ----------------
struct WArgs { const float* Ww[2]; const float* Wb[2]; };

__global__ __launch_bounds__(128) void wconv_kernel(WArgs A)
{
    int tid = threadIdx.x;
    int n0  = blockIdx.x * 256;
    int o0  = blockIdx.y * 32;
    int sb  = blockIdx.z;
    int sel = sb >> 1;

    __shared__ __align__(16) float2 Xs[32 * 128];
    __shared__ __align__(16) float2 Ws[32 * 32];

    f2 acc[32];
    #pragma unroll
    for (int j = 0; j < 32; ++j) acc[j] = 0ULL;

    const float* src = g_outc + sb * (INTER * Nn) + n0 + 2 * tid;
    const float* Ww = A.Ww[sel];

    for (int i0 = 0; i0 < INTER; i0 += 32) {
        #pragma unroll 8
        for (int k = 0; k < 32; ++k)
            Xs[k * 128 + tid] = *(const float2*)(src + (i0 + k) * Nn);
        #pragma unroll
        for (int r = 0; r < 8; ++r) {
            int idx = tid + r * 128;
            int j = idx >> 5, k = idx & 31;
            float w = Ww[(o0 + j) * INTER + i0 + k];
            Ws[j * 32 + k] = make_float2(w, w);
        }
        __syncthreads();
        #pragma unroll 2
        for (int k = 0; k < 32; k += 2) {
            f2 xv0 = *(const f2*)&Xs[k * 128 + tid];
            f2 xv1 = *(const f2*)&Xs[(k + 1) * 128 + tid];
            #pragma unroll
            for (int j = 0; j < 32; ++j) {
                F4 w = *(const F4*)&Ws[j * 32 + k];
                acc[j] = fma2(w.a, xv0, acc[j]);
                acc[j] = fma2(w.b, xv1, acc[j]);
            }
        }
        __syncthreads();
    }

    float* dst = g_wy + sb * (Cc * Nn) + n0 + 2 * tid;
    const float* Wb = A.Wb[sel];
    #pragma unroll
    for (int j = 0; j < 32; ++j) {
        float lo, hi;
        unpack2(acc[j], lo, hi);
        float bb = Wb[o0 + j];
        *(float2*)(dst + (o0 + j) * Nn) = make_float2(lo + bb, hi + bb);
    }
}

// ---------------- Kernel 4: BN stats ----------------
__global__ __launch_bounds__(256) void stats_kernel()
{
    int sel = blockIdx.x / Cc;
    int o   = blockIdx.x % Cc;
    int tid = threadIdx.x;
    const float4* r0 = (const float4*)(g_wy + ((sel*Bb + 0) * Cc + o) * Nn);
    const float4* r1 = (const float4*)(g_wy + ((sel*Bb + 1) * Cc + o) * Nn);

    float s = 0.f, s2 = 0.f;
    for (int i = tid; i < Nn/4; i += 256) {
        float4 a = r0[i], c = r1[i];
        s += a.x + a.y + a.z + a.w;
        s += c.x + c.y + c.z + c.w;
        s2 = fmaf(a.x, a.x, s2); s2 = fmaf(a.y, a.y, s2);
        s2 = fmaf(a.z, a.z, s2); s2 = fmaf(a.w, a.w, s2);
        s2 = fmaf(c.x, c.x, s2); s2 = fmaf(c.y, c.y, s2);
        s2 = fmaf(c.z, c.z, s2); s2 = fmaf(c.w, c.w, s2);
    }
    __shared__ float sh[256], sh2[256];
    sh[tid] = s; sh2[tid] = s2;
    __syncthreads();
    for (int st = 128; st > 0; st >>= 1) {
        if (tid < st) { sh[tid] += sh[tid + st]; sh2[tid] += sh2[tid + st]; }
        __syncthreads();
    }
    if (tid == 0) {
        float mean = sh[0] * (1.0f / (Bb * Nn));
        float var  = sh2[0] * (1.0f / (Bb * Nn)) - mean * mean;
        g_mean[blockIdx.x] = mean;
        g_rstd[blockIdx.x] = rsqrtf(var + EPSf);
    }
}

// ---------------- Kernel 5: BN apply + residual + ReLU ----------------
struct ApplyArgs {
    const float* x[2];
    const float* gam[2]; const float* bet[2];
};

__global__ __launch_bounds__(256) void apply_kernel(ApplyArgs A, float* __restrict__ out)
{
    int i4 = blockIdx.x * 256 + threadIdx.x;
    int idx = i4 * 4;
    int per = Bb * Cc * Nn;
    int sel = idx / per;
    int loc = idx - sel * per;
    int o   = (loc / Nn) % Cc;
    float m  = g_mean[sel*Cc + o];
    float rs = g_rstd[sel*Cc + o];
    float ga = A.gam[sel][o], be = A.bet[sel][o];
    float4 wv = *(const float4*)(g_wy + idx);
    float4 xv = *(const float4*)(A.x[sel] + loc);
    float4 r;
    r.x = fmaxf(fmaf((wv.x - m) * rs, ga, be) + xv.x, 0.f);
    r.y = fmaxf(fmaf((wv.y - m) * rs, ga, be) + xv.y, 0.f);
    r.z = fmaxf(fmaf((wv.z - m) * rs, ga, be) + xv.z, 0.f);
    r.w = fmaxf(fmaf((wv.w - m) * rs, ga, be) + xv.w, 0.f);
    *(float4*)(out + idx) = r;
}

// ---------------- launch ----------------
extern "C" void kernel_launch(void* const* d_in, const int* in_sizes, int n_in,
                              void* d_out, int out_size)
{
    ProjArgs P; WArgs W; ApplyArgs AP;
    for (int s = 0; s < 2; ++s) {
        P.x[s]  = (const float*)d_in[s];
        P.gw[s] = (const float*)d_in[2 + s*10 + 0];
        P.gb[s] = (const float*)d_in[2 + s*10 + 1];
        P.tw[s] = (const float*)d_in[2 + s*10 + 2];
        P.tb[s] = (const float*)d_in[2 + s*10 + 3];
        P.pw[s] = (const float*)d_in[2 + s*10 + 4];
        P.pb[s] = (const float*)d_in[2 + s*10 + 5];
        W.Ww[s] = (const float*)d_in[2 + s*10 + 6];
        W.Wb[s] = (const float*)d_in[2 + s*10 + 7];
        AP.x[s]   = (const float*)d_in[s];
        AP.gam[s] = (const float*)d_in[2 + s*10 + 8];
        AP.bet[s] = (const float*)d_in[2 + s*10 + 9];
    }

    proj_kernel    <<<dim3(9, Gg, SEL*Bb), 128>>>(P);
    attn_mma_kernel<<<dim3(18, Gg, SEL*Bb), 128>>>();
    wconv_kernel   <<<dim3(9, Cc/32, SEL*Bb), 128>>>(W);
    stats_kernel   <<<SEL*Cc, 256>>>();
    apply_kernel   <<<(SEL*Bb*Cc*Nn)/1024, 256>>>(AP, (float*)d_out);
}

// round 9
// speedup vs baseline: 4.3786x; 1.2713x over previous
#include <cuda_runtime.h>
#include <cstdint>

typedef unsigned int u32;
typedef unsigned short u16;

#define SEL   2
#define Bb    2
#define Cc    256
#define Nn    2304
#define Gg    8
#define CGd   16
#define INTER 128
#define EPSf  1e-5f
#define LOG2E 1.4426950408889634f

// ---------------- scratch ----------------
__device__ u16  g_xTh[SEL*Bb*Nn*Cc];        // [sb][n][c] bf16 hi (x transposed)
__device__ u16  g_xTl[SEL*Bb*Nn*Cc];        // lo
__device__ u16  g_thQ[SEL*Bb*Gg*Nn*32];     // [bg][n][16 hi | 16 lo], theta*log2e
__device__ u16  g_phK[SEL*Bb*Gg*Nn*32];     // [bg][n][16 hi | 16 lo], phi
__device__ u16  g_vH [SEL*Bb*Gg*CGd*Nn];    // [bg][d][n] hi
__device__ u16  g_vL [SEL*Bb*Gg*CGd*Nn];    // lo
__device__ u16  g_ocTh[SEL*Bb*Nn*INTER];    // [sb][n][i] attention out hi
__device__ u16  g_ocTl[SEL*Bb*Nn*INTER];    // lo
__device__ float g_wy  [SEL*Bb*Cc*Nn];
__device__ float g_mean[SEL*Cc];
__device__ float g_rstd[SEL*Cc];

// ---------------- helpers ----------------
__device__ __forceinline__ u32 smem_u32(const void* p) {
    u32 a;
    asm("{ .reg .u64 t; cvta.to.shared.u64 t, %1; cvt.u32.u64 %0, t; }" : "=r"(a) : "l"(p));
    return a;
}
__device__ __forceinline__ u32 cvt2bf(float hi, float lo) {
    u32 d; asm("cvt.rn.bf16x2.f32 %0, %1, %2;" : "=r"(d) : "f"(hi), "f"(lo)); return d;
}
__device__ __forceinline__ float bflo(u32 w) { return __uint_as_float(w << 16); }
__device__ __forceinline__ float bfhi(u32 w) { return __uint_as_float(w & 0xFFFF0000u); }

__device__ __forceinline__ void ldsm4(u32* r, u32 a) {
    asm volatile("ldmatrix.sync.aligned.m8n8.x4.shared.b16 {%0,%1,%2,%3}, [%4];"
        : "=r"(r[0]), "=r"(r[1]), "=r"(r[2]), "=r"(r[3]) : "r"(a));
}
__device__ __forceinline__ void ldsm2(u32* r, u32 a) {
    asm volatile("ldmatrix.sync.aligned.m8n8.x2.shared.b16 {%0,%1}, [%2];"
        : "=r"(r[0]), "=r"(r[1]) : "r"(a));
}
__device__ __forceinline__ void mma_bf16(float* c, const u32* a, const u32* b) {
    asm volatile("mma.sync.aligned.m16n8k16.row.col.f32.bf16.bf16.f32 "
        "{%0,%1,%2,%3}, {%4,%5,%6,%7}, {%8,%9}, {%0,%1,%2,%3};"
        : "+f"(c[0]), "+f"(c[1]), "+f"(c[2]), "+f"(c[3])
        : "r"(a[0]), "r"(a[1]), "r"(a[2]), "r"(a[3]), "r"(b[0]), "r"(b[1]));
}
__device__ __forceinline__ float exp2f_fast(float t) {
    float z = t + 12582912.0f;
    int   r = __float_as_int(z) - 0x4b400000;
    float f = t - (z - 12582912.0f);
    float p = 9.6181291e-3f;                 // degree-4 (rel err ~4e-5)
    p = fmaf(p, f, 5.5504109e-2f);
    p = fmaf(p, f, 2.4022651e-1f);
    p = fmaf(p, f, 6.9314718e-1f);
    p = fmaf(p, f, 1.0f);
    return __int_as_float(__float_as_int(p) + (r << 23));
}

// ---------------- Kernel 0: x -> transposed bf16 hi/lo [sb][n][c] ----------------
struct XArgs { const float* x[2]; };

__global__ __launch_bounds__(256) void xcvt_kernel(XArgs A)
{
    // grid (18, 4)
    int n0 = blockIdx.x * 128;
    int sb = blockIdx.y;
    int sel = sb >> 1, b = sb & 1;
    const float* x = A.x[sel] + (size_t)b * Cc * Nn;
    __shared__ float T[64][132];
    int tid = threadIdx.x;

    for (int c0 = 0; c0 < Cc; c0 += 64) {
        int nn = tid & 127, ch = tid >> 7;
        #pragma unroll 8
        for (int i = 0; i < 32; ++i)
            T[ch + 2*i][nn] = x[(size_t)(c0 + ch + 2*i) * Nn + n0 + nn];
        __syncthreads();
        int n = tid >> 1, kh = (tid & 1) * 32;
        u32 hb[16], lb[16];
        #pragma unroll
        for (int j = 0; j < 16; ++j) {
            float v0 = T[kh + 2*j][n], v1 = T[kh + 2*j + 1][n];
            u32 hh = cvt2bf(v1, v0);
            hb[j] = hh;
            lb[j] = cvt2bf(v1 - bfhi(hh), v0 - bflo(hh));
        }
        size_t off = ((size_t)sb * Nn + n0 + n) * Cc + c0 + kh;
        uint4* dh = (uint4*)(g_xTh + off);
        uint4* dl = (uint4*)(g_xTl + off);
        dh[0] = make_uint4(hb[0],hb[1],hb[2],hb[3]);
        dh[1] = make_uint4(hb[4],hb[5],hb[6],hb[7]);
        dh[2] = make_uint4(hb[8],hb[9],hb[10],hb[11]);
        dh[3] = make_uint4(hb[12],hb[13],hb[14],hb[15]);
        dl[0] = make_uint4(lb[0],lb[1],lb[2],lb[3]);
        dl[1] = make_uint4(lb[4],lb[5],lb[6],lb[7]);
        dl[2] = make_uint4(lb[8],lb[9],lb[10],lb[11]);
        dl[3] = make_uint4(lb[12],lb[13],lb[14],lb[15]);
        __syncthreads();
    }
}

// ---------------- Kernel 1: grouped projections via bf16 mma ----------------
// GEMM Y[j,n] = W[j,c] x[c,n], j-tile 64 (p = jt>>1: 0 theta, 1 phi, 2 g).
// 3-term: Wh Xh + Wh Xl + Wl Xh.
struct PjArgs {
    const float* w[2][3];      // [sel][theta, phi, g]
    const float* bias[2][3];
};

__global__ __launch_bounds__(128) void projmma_kernel(PjArgs A)
{
    // grid (18, 6, 4)
    __shared__ __align__(16) union {
        struct {
            u16 Ah[64*40], Al[64*40];     // [j][k-chunk 32 + pad]
            u16 Bh[128*40], Bl[128*40];   // [n][k]
        } m;
        float Cd[64*132];
    } SM;

    int tid = threadIdx.x, lane = tid & 31, wid = tid >> 5;
    int n0 = blockIdx.x * 128;
    int jt = blockIdx.y;
    int sb = blockIdx.z, sel = sb >> 1;
    int p  = jt >> 1;
    int g0 = (jt & 1) * 4;

    const float* wsrc = A.w[sel][p] + (size_t)(g0 * CGd) * Cc;
    const u16* xh = g_xTh + (size_t)sb * Nn * Cc;
    const u16* xl = g_xTl + (size_t)sb * Nn * Cc;

    float C[16][4];
    #pragma unroll
    for (int i = 0; i < 16; ++i)
        #pragma unroll
        for (int q = 0; q < 4; ++q) C[i][q] = 0.f;

    u32 AhB = smem_u32(SM.m.Ah), AlB = smem_u32(SM.m.Al);
    u32 BhB = smem_u32(SM.m.Bh), BlB = smem_u32(SM.m.Bl);

    int ar  = (lane & 7) + ((lane >> 3) & 1) * 8;
    int acb = (lane >> 4) * 16;
    int brow = (lane & 7) + ((lane >> 4) & 1) * 8;
    int bcb  = ((lane >> 3) & 1) * 16;

    for (int c0 = 0; c0 < Cc; c0 += 32) {
        // A fill: 64 j x 32 c (fp32 -> bf16 hi/lo)
        {
            int j = tid >> 1, kh2 = (tid & 1) * 16;
            const float* wr = wsrc + (size_t)j * Cc + c0 + kh2;
            u32 hb[8], lb[8];
            #pragma unroll
            for (int q = 0; q < 8; ++q) {
                float v0 = wr[2*q], v1 = wr[2*q + 1];
                u32 hh = cvt2bf(v1, v0);
                hb[q] = hh;
                lb[q] = cvt2bf(v1 - bfhi(hh), v0 - bflo(hh));
            }
            uint4* dh = (uint4*)(SM.m.Ah + j * 40 + kh2);
            uint4* dl = (uint4*)(SM.m.Al + j * 40 + kh2);
            dh[0] = make_uint4(hb[0],hb[1],hb[2],hb[3]);
            dh[1] = make_uint4(hb[4],hb[5],hb[6],hb[7]);
            dl[0] = make_uint4(lb[0],lb[1],lb[2],lb[3]);
            dl[1] = make_uint4(lb[4],lb[5],lb[6],lb[7]);
        }
        // B fill: 128 n x 32 c, straight copy
        {
            size_t off = (size_t)(n0 + tid) * Cc + c0;
            const uint4* sh = (const uint4*)(xh + off);
            const uint4* sl = (const uint4*)(xl + off);
            uint4* dh = (uint4*)(SM.m.Bh + tid * 40);
            uint4* dl = (uint4*)(SM.m.Bl + tid * 40);
            dh[0]=sh[0]; dh[1]=sh[1]; dh[2]=sh[2]; dh[3]=sh[3];
            dl[0]=sl[0]; dl[1]=sl[1]; dl[2]=sl[2]; dl[3]=sl[3];
        }
        __syncthreads();

        #pragma unroll
        for (int kk = 0; kk < 2; ++kk) {
            u32 ah[4], al[4];
            u32 aoff = (u32)(wid*16 + ar) * 80 + kk*32 + acb;
            ldsm4(ah, AhB + aoff);
            ldsm4(al, AlB + aoff);
            #pragma unroll
            for (int nn = 0; nn < 8; ++nn) {
                u32 bh[4], bl[4];
                u32 boff = (u32)(nn*16 + brow) * 80 + kk*32 + bcb;
                ldsm4(bh, BhB + boff);
                ldsm4(bl, BlB + boff);
                mma_bf16(C[2*nn],   ah, bh);
                mma_bf16(C[2*nn],   al, bh);
                mma_bf16(C[2*nn],   ah, bl);
                mma_bf16(C[2*nn+1], ah, bh+2);
                mma_bf16(C[2*nn+1], al, bh+2);
                mma_bf16(C[2*nn+1], ah, bl+2);
            }
        }
        __syncthreads();
    }

    // dump C to smem [64 j][132]
    {
        int gq = lane >> 2, tg = lane & 3;
        #pragma unroll
        for (int nf = 0; nf < 16; ++nf) {
            int r = wid*16 + gq, col = nf*8 + 2*tg;
            *(float2*)&SM.Cd[r*132 + col]       = make_float2(C[nf][0], C[nf][1]);
            *(float2*)&SM.Cd[(r+8)*132 + col]   = make_float2(C[nf][2], C[nf][3]);
        }
    }
    __syncthreads();

    if (p < 2) {
        // theta / phi: thread = n, write [bg][n][16h|16l]
        const float* bias = A.bias[sel][p];
        #pragma unroll
        for (int gg = 0; gg < 4; ++gg) {
            int gabs = g0 + gg;
            int bg = sb * Gg + gabs;
            u32 hb[8], lb[8];
            #pragma unroll
            for (int q = 0; q < 8; ++q) {
                float v0 = SM.Cd[(gg*16 + 2*q)*132 + tid]   + bias[gabs*CGd + 2*q];
                float v1 = SM.Cd[(gg*16 + 2*q+1)*132 + tid] + bias[gabs*CGd + 2*q + 1];
                if (p == 0) { v0 *= LOG2E; v1 *= LOG2E; }
                u32 hh = cvt2bf(v1, v0);
                hb[q] = hh;
                lb[q] = cvt2bf(v1 - bfhi(hh), v0 - bflo(hh));
            }
            u16* dst = (p == 0 ? g_thQ : g_phK) + (size_t)(bg * Nn + n0 + tid) * 32;
            uint4* d4 = (uint4*)dst;
            d4[0] = make_uint4(hb[0],hb[1],hb[2],hb[3]);
            d4[1] = make_uint4(hb[4],hb[5],hb[6],hb[7]);
            d4[2] = make_uint4(lb[0],lb[1],lb[2],lb[3]);
            d4[3] = make_uint4(lb[4],lb[5],lb[6],lb[7]);
        }
    } else {
        // V: write [bg][d][n] hi/lo
        const float* bias = A.bias[sel][2];
        int half = tid >> 6, np = tid & 63;
        #pragma unroll 4
        for (int rr = 0; rr < 32; ++rr) {
            int j = rr*2 + half;
            int gabs = g0 + (j >> 4), d = j & 15;
            float bv = bias[gabs*CGd + d];
            float v0 = SM.Cd[j*132 + 2*np]     + bv;
            float v1 = SM.Cd[j*132 + 2*np + 1] + bv;
            u32 hh = cvt2bf(v1, v0);
            size_t off = ((size_t)(sb*Gg + gabs)*CGd + d) * Nn + n0 + 2*np;
            *(u32*)(g_vH + off) = hh;
            *(u32*)(g_vL + off) = cvt2bf(v1 - bfhi(hh), v0 - bflo(hh));
        }
    }
}

// ---------------- Kernel 2: bf16 mma flash attention ----------------
#define QLD 40
#define VLD 136
#define OQ  0
#define OK  10240
#define OVH 20480
#define OVL 27008
#define SMSZ 31360

__global__ __launch_bounds__(128) void attn_mma_kernel()
{
    __shared__ __align__(16) char SM[SMSZ];
    u16* Qs = (u16*)(SM + OQ);
    u16* Ks = (u16*)(SM + OK);
    u16* VHs = (u16*)(SM + OVH);
    u16* VLs = (u16*)(SM + OVL);

    int tid = threadIdx.x, lane = tid & 31, wid = tid >> 5;
    int g = blockIdx.y, sbz = blockIdx.z;
    int bg = sbz * Gg + g;
    int n0 = blockIdx.x * 128;

    const u16* thq = g_thQ + (size_t)bg * Nn * 32;
    const u16* phk = g_phK + (size_t)bg * Nn * 32;
    const u16* vh  = g_vH + (size_t)bg * CGd * Nn;
    const u16* vl  = g_vL + (size_t)bg * CGd * Nn;

    // Q fill
    {
        const uint4* src = (const uint4*)(thq + (size_t)(n0 + tid) * 32);
        uint4* dst = (uint4*)(Qs + tid * QLD);
        dst[0] = src[0]; dst[1] = src[1]; dst[2] = src[2]; dst[3] = src[3];
    }
    // VH constant rows 16..23 (row 16 = ones)
    #pragma unroll
    for (int i = 0; i < 8; ++i) {
        int r = 16 + i;
        VHs[r * VLD + tid] = (r == 16) ? (u16)0x3F80 : (u16)0;
    }
    __syncthreads();

    u32 SMB = smem_u32(SM);
    u32 QB = SMB + OQ, KB = SMB + OK, VHB = SMB + OVH, VLB = SMB + OVL;

    u32 qh[2][4], ql[2][4];
    {
        int ar  = (lane & 7) + ((lane >> 3) & 1) * 8;
        int acb = (lane >> 4) * 16;
        #pragma unroll
        for (int mi = 0; mi < 2; ++mi) {
            u32 ad = QB + (u32)(wid * 32 + mi * 16 + ar) * 80 + acb;
            ldsm4(qh[mi], ad);
            ldsm4(ql[mi], ad + 32);
        }
    }

    float O[2][3][4];
    #pragma unroll
    for (int mi = 0; mi < 2; ++mi)
        #pragma unroll
        for (int nt = 0; nt < 3; ++nt)
            #pragma unroll
            for (int q = 0; q < 4; ++q) O[mi][nt][q] = 0.f;

    int krow = (lane & 7) + ((lane >> 4) & 1) * 8;   // x4 B-layout rows
    int kcb  = ((lane >> 3) & 1) * 16;
    int vrow = (lane & 7);
    int vcb  = ((lane >> 3) & 1) * 16;

    for (int t = 0; t < 18; ++t) {
        int t0 = t * 128;
        {
            const uint4* src = (const uint4*)(phk + (size_t)(t0 + tid) * 32);
            uint4* dst = (uint4*)(Ks + tid * QLD);
            dst[0] = src[0]; dst[1] = src[1]; dst[2] = src[2]; dst[3] = src[3];
        }
        {
            int d = tid >> 3, blk = (tid & 7) * 16;
            const uint4* sh = (const uint4*)(vh + (size_t)d * Nn + t0 + blk);
            const uint4* sl = (const uint4*)(vl + (size_t)d * Nn + t0 + blk);
            uint4* dh = (uint4*)(VHs + d * VLD + blk);
            uint4* dl = (uint4*)(VLs + d * VLD + blk);
            dh[0] = sh[0]; dh[1] = sh[1];
            dl[0] = sl[0]; dl[1] = sl[1];
        }
        __syncthreads();

        #pragma unroll 2
        for (int c = 0; c < 8; ++c) {
            u32 khb4[4], klb4[4];
            {
                u32 a = KB + (u32)(c * 16 + krow) * 80 + kcb;
                ldsm4(khb4, a);
                ldsm4(klb4, a + 32);
            }
            float C[2][2][4];
            #pragma unroll
            for (int mi = 0; mi < 2; ++mi)
                #pragma unroll
                for (int s = 0; s < 2; ++s) {
                    C[mi][s][0] = 0.f; C[mi][s][1] = 0.f; C[mi][s][2] = 0.f; C[mi][s][3] = 0.f;
                    mma_bf16(C[mi][s], qh[mi], khb4 + 2*s);
                    mma_bf16(C[mi][s], qh[mi], klb4 + 2*s);
                    mma_bf16(C[mi][s], ql[mi], khb4 + 2*s);
                }
            u32 pha[2][4], pla[2][4];
            #pragma unroll
            for (int mi = 0; mi < 2; ++mi)
                #pragma unroll
                for (int s = 0; s < 2; ++s) {
                    float p0 = exp2f_fast(C[mi][s][0]);
                    float p1 = exp2f_fast(C[mi][s][1]);
                    float p2 = exp2f_fast(C[mi][s][2]);
                    float p3 = exp2f_fast(C[mi][s][3]);
                    u32 w01 = cvt2bf(p1, p0);
                    u32 w23 = cvt2bf(p3, p2);
                    pha[mi][2*s]     = w01;
                    pha[mi][2*s + 1] = w23;
                    pla[mi][2*s]     = cvt2bf(p1 - bfhi(w01), p0 - bflo(w01));
                    pla[mi][2*s + 1] = cvt2bf(p3 - bfhi(w23), p2 - bflo(w23));
                }
            u32 vhbf[3][2], vlbf[2][2];
            {
                u32 vbase = (u32)vrow * 272 + (u32)vcb + (u32)c * 32;
                #pragma unroll
                for (int nt = 0; nt < 3; ++nt)
                    ldsm2(vhbf[nt], VHB + vbase + (u32)nt * 8 * 272);
                #pragma unroll
                for (int nt = 0; nt < 2; ++nt)
                    ldsm2(vlbf[nt], VLB + vbase + (u32)nt * 8 * 272);
            }
            #pragma unroll
            for (int mi = 0; mi < 2; ++mi) {
                #pragma unroll
                for (int nt = 0; nt < 3; ++nt) {
                    mma_bf16(O[mi][nt], pha[mi], vhbf[nt]);
                    mma_bf16(O[mi][nt], pla[mi], vhbf[nt]);
                }
                #pragma unroll
                for (int nt = 0; nt < 2; ++nt)
                    mma_bf16(O[mi][nt], pha[mi], vlbf[nt]);
            }
        }
        __syncthreads();
    }

    // Epilogue: dump O to smem (stride 26), normalize, emit bf16 hi/lo [n][i]
    float* Es = (float*)(SM + OK);
    {
        int gq = lane >> 2, tg = lane & 3;
        #pragma unroll
        for (int mi = 0; mi < 2; ++mi)
            #pragma unroll
            for (int nt = 0; nt < 3; ++nt) {
                int r = wid * 32 + mi * 16 + gq;
                int col = nt * 8 + 2 * tg;
                Es[r * 26 + col]           = O[mi][nt][0];
                Es[r * 26 + col + 1]       = O[mi][nt][1];
                Es[(r + 8) * 26 + col]     = O[mi][nt][2];
                Es[(r + 8) * 26 + col + 1] = O[mi][nt][3];
            }
    }
    __syncthreads();
    {
        float inv = 1.0f / Es[tid * 26 + 16];
        u32 hb[8], lb[8];
        #pragma unroll
        for (int q = 0; q < 8; ++q) {
            float v0 = Es[tid * 26 + 2*q]     * inv;
            float v1 = Es[tid * 26 + 2*q + 1] * inv;
            u32 hh = cvt2bf(v1, v0);
            hb[q] = hh;
            lb[q] = cvt2bf(v1 - bfhi(hh), v0 - bflo(hh));
        }
        size_t off = ((size_t)sbz * Nn + n0 + tid) * INTER + g * CGd;
        uint4* dh = (uint4*)(g_ocTh + off);
        uint4* dl = (uint4*)(g_ocTl + off);
        dh[0] = make_uint4(hb[0],hb[1],hb[2],hb[3]);
        dh[1] = make_uint4(hb[4],hb[5],hb[6],hb[7]);
        dl[0] = make_uint4(lb[0],lb[1],lb[2],lb[3]);
        dl[1] = make_uint4(lb[4],lb[5],lb[6],lb[7]);
    }
}

// ---------------- Kernel 3: W conv via bf16 mma ----------------
struct WcArgs { const float* Ww[2]; const float* Wb[2]; };

__global__ __launch_bounds__(128) void wconvmma_kernel(WcArgs A)
{
    // grid (18, 4, 4): n-tile 128, o-tile 64, sb
    __shared__ __align__(16) struct {
        u16 Ah[64*40], Al[64*40];
        u16 Bh[128*40], Bl[128*40];
    } SM;

    int tid = threadIdx.x, lane = tid & 31, wid = tid >> 5;
    int n0 = blockIdx.x * 128;
    int o0 = blockIdx.y * 64;
    int sb = blockIdx.z, sel = sb >> 1;

    const float* Ww = A.Ww[sel];
    const u16* och = g_ocTh + (size_t)sb * Nn * INTER;
    const u16* ocl = g_ocTl + (size_t)sb * Nn * INTER;

    float C[16][4];
    #pragma unroll
    for (int i = 0; i < 16; ++i)
        #pragma unroll
        for (int q = 0; q < 4; ++q) C[i][q] = 0.f;

    u32 AhB = smem_u32(SM.Ah), AlB = smem_u32(SM.Al);
    u32 BhB = smem_u32(SM.Bh), BlB = smem_u32(SM.Bl);

    int ar  = (lane & 7) + ((lane >> 3) & 1) * 8;
    int acb = (lane >> 4) * 16;
    int brow = (lane & 7) + ((lane >> 4) & 1) * 8;
    int bcb  = ((lane >> 3) & 1) * 16;

    for (int c0 = 0; c0 < INTER; c0 += 32) {
        {
            int j = tid >> 1, kh2 = (tid & 1) * 16;
            const float* wr = Ww + (size_t)(o0 + j) * INTER + c0 + kh2;
            u32 hb[8], lb[8];
            #pragma unroll
            for (int q = 0; q < 8; ++q) {
                float v0 = wr[2*q], v1 = wr[2*q + 1];
                u32 hh = cvt2bf(v1, v0);
                hb[q] = hh;
                lb[q] = cvt2bf(v1 - bfhi(hh), v0 - bflo(hh));
            }
            uint4* dh = (uint4*)(SM.Ah + j * 40 + kh2);
            uint4* dl = (uint4*)(SM.Al + j * 40 + kh2);
            dh[0] = make_uint4(hb[0],hb[1],hb[2],hb[3]);
            dh[1] = make_uint4(hb[4],hb[5],hb[6],hb[7]);
            dl[0] = make_uint4(lb[0],lb[1],lb[2],lb[3]);
            dl[1] = make_uint4(lb[4],lb[5],lb[6],lb[7]);
        }
        {
            size_t off = (size_t)(n0 + tid) * INTER + c0;
            const uint4* sh = (const uint4*)(och + off);
            const uint4* sl = (const uint4*)(ocl + off);
            uint4* dh = (uint4*)(SM.Bh + tid * 40);
            uint4* dl = (uint4*)(SM.Bl + tid * 40);
            dh[0]=sh[0]; dh[1]=sh[1]; dh[2]=sh[2]; dh[3]=sh[3];
            dl[0]=sl[0]; dl[1]=sl[1]; dl[2]=sl[2]; dl[3]=sl[3];
        }
        __syncthreads();

        #pragma unroll
        for (int kk = 0; kk < 2; ++kk) {
            u32 ah[4], al[4];
            u32 aoff = (u32)(wid*16 + ar) * 80 + kk*32 + acb;
            ldsm4(ah, AhB + aoff);
            ldsm4(al, AlB + aoff);
            #pragma unroll
            for (int nn = 0; nn < 8; ++nn) {
                u32 bh[4], bl[4];
                u32 boff = (u32)(nn*16 + brow) * 80 + kk*32 + bcb;
                ldsm4(bh, BhB + boff);
                ldsm4(bl, BlB + boff);
                mma_bf16(C[2*nn],   ah, bh);
                mma_bf16(C[2*nn],   al, bh);
                mma_bf16(C[2*nn],   ah, bl);
                mma_bf16(C[2*nn+1], ah, bh+2);
                mma_bf16(C[2*nn+1], al, bh+2);
                mma_bf16(C[2*nn+1], ah, bl+2);
            }
        }
        __syncthreads();
    }

    // Epilogue: bias + direct store to g_wy[o][n]
    {
        const float* Wb = A.Wb[sel];
        int gq = lane >> 2, tg = lane & 3;
        int o_r = o0 + wid*16 + gq;
        float b0 = Wb[o_r], b1 = Wb[o_r + 8];
        #pragma unroll
        for (int nf = 0; nf < 16; ++nf) {
            int n_c = n0 + nf*8 + 2*tg;
            *(float2*)&g_wy[((size_t)sb*Cc + o_r) * Nn + n_c] =
                make_float2(C[nf][0] + b0, C[nf][1] + b0);
            *(float2*)&g_wy[((size_t)sb*Cc + o_r + 8) * Nn + n_c] =
                make_float2(C[nf][2] + b1, C[nf][3] + b1);
        }
    }
}

// ---------------- Kernel 4: BN stats ----------------
__global__ __launch_bounds__(256) void stats_kernel()
{
    int sel = blockIdx.x / Cc;
    int o   = blockIdx.x % Cc;
    int tid = threadIdx.x;
    const float4* r0 = (const float4*)(g_wy + ((size_t)(sel*Bb + 0) * Cc + o) * Nn);
    const float4* r1 = (const float4*)(g_wy + ((size_t)(sel*Bb + 1) * Cc + o) * Nn);

    float s = 0.f, s2 = 0.f;
    for (int i = tid; i < Nn/4; i += 256) {
        float4 a = r0[i], c = r1[i];
        s += a.x + a.y + a.z + a.w;
        s += c.x + c.y + c.z + c.w;
        s2 = fmaf(a.x, a.x, s2); s2 = fmaf(a.y, a.y, s2);
        s2 = fmaf(a.z, a.z, s2); s2 = fmaf(a.w, a.w, s2);
        s2 = fmaf(c.x, c.x, s2); s2 = fmaf(c.y, c.y, s2);
        s2 = fmaf(c.z, c.z, s2); s2 = fmaf(c.w, c.w, s2);
    }
    __shared__ float sh[256], sh2[256];
    sh[tid] = s; sh2[tid] = s2;
    __syncthreads();
    for (int st = 128; st > 0; st >>= 1) {
        if (tid < st) { sh[tid] += sh[tid + st]; sh2[tid] += sh2[tid + st]; }
        __syncthreads();
    }
    if (tid == 0) {
        float mean = sh[0] * (1.0f / (Bb * Nn));
        float var  = sh2[0] * (1.0f / (Bb * Nn)) - mean * mean;
        g_mean[blockIdx.x] = mean;
        g_rstd[blockIdx.x] = rsqrtf(var + EPSf);
    }
}

// ---------------- Kernel 5: BN apply + residual + ReLU ----------------
struct ApplyArgs {
    const float* x[2];
    const float* gam[2]; const float* bet[2];
};

__global__ __launch_bounds__(256) void apply_kernel(ApplyArgs A, float* __restrict__ out)
{
    int i4 = blockIdx.x * 256 + threadIdx.x;
    int idx = i4 * 4;
    int per = Bb * Cc * Nn;
    int sel = idx / per;
    int loc = idx - sel * per;
    int o   = (loc / Nn) % Cc;
    float m  = g_mean[sel*Cc + o];
    float rs = g_rstd[sel*Cc + o];
    float ga = A.gam[sel][o], be = A.bet[sel][o];
    float4 wv = *(const float4*)(g_wy + idx);
    float4 xv = *(const float4*)(A.x[sel] + loc);
    float4 r;
    r.x = fmaxf(fmaf((wv.x - m) * rs, ga, be) + xv.x, 0.f);
    r.y = fmaxf(fmaf((wv.y - m) * rs, ga, be) + xv.y, 0.f);
    r.z = fmaxf(fmaf((wv.z - m) * rs, ga, be) + xv.z, 0.f);
    r.w = fmaxf(fmaf((wv.w - m) * rs, ga, be) + xv.w, 0.f);
    *(float4*)(out + idx) = r;
}

// ---------------- launch ----------------
extern "C" void kernel_launch(void* const* d_in, const int* in_sizes, int n_in,
                              void* d_out, int out_size)
{
    XArgs X; PjArgs P; WcArgs W; ApplyArgs AP;
    for (int s = 0; s < 2; ++s) {
        X.x[s] = (const float*)d_in[s];
        P.w[s][0]    = (const float*)d_in[2 + s*10 + 2];   // theta_w
        P.bias[s][0] = (const float*)d_in[2 + s*10 + 3];
        P.w[s][1]    = (const float*)d_in[2 + s*10 + 4];   // phi_w
        P.bias[s][1] = (const float*)d_in[2 + s*10 + 5];
        P.w[s][2]    = (const float*)d_in[2 + s*10 + 0];   // g_w
        P.bias[s][2] = (const float*)d_in[2 + s*10 + 1];
        W.Ww[s] = (const float*)d_in[2 + s*10 + 6];
        W.Wb[s] = (const float*)d_in[2 + s*10 + 7];
        AP.x[s]   = (const float*)d_in[s];
        AP.gam[s] = (const float*)d_in[2 + s*10 + 8];
        AP.bet[s] = (const float*)d_in[2 + s*10 + 9];
    }

    xcvt_kernel    <<<dim3(18, 4), 256>>>(X);
    projmma_kernel <<<dim3(18, 6, 4), 128>>>(P);
    attn_mma_kernel<<<dim3(18, Gg, SEL*Bb), 128>>>();
    wconvmma_kernel<<<dim3(18, 4, 4), 128>>>(W);
    stats_kernel   <<<SEL*Cc, 256>>>();
    apply_kernel   <<<(SEL*Bb*Cc*Nn)/1024, 256>>>(AP, (float*)d_out);
}